// round 8
// baseline (speedup 1.0000x reference)
#include <cuda_runtime.h>
#include <cuda_fp16.h>
#include <math.h>
#include <stdint.h>

#define D_TOT   147456
#define N_MEM   6
#define NPX     4096
#define PPL     4752            // padded plane: 66*72 halves

// ---------------- device scratch (no allocation allowed) -------------------
__device__ float g_minmax[2];
__device__ float g_m1[D_TOT];
__device__ float g_g1[D_TOT];
__device__ float g_ws[N_MEM * D_TOT];
__device__ __align__(16) __half g_wU[N_MEM * 16 * 128 * 128];   // [n][comp][oc][ic]
__device__ __align__(16) __half g_xp[(size_t)48 * 128 * PPL];   // padded fp16 x

// ---------------- helpers ---------------------------------------------------
__device__ __forceinline__ uint32_t smem_u32(const void* p) {
    uint32_t a;
    asm("{ .reg .u64 t; cvta.to.shared.u64 t, %1; cvt.u32.u64 %0, t; }"
        : "=r"(a) : "l"(p));
    return a;
}
__device__ __forceinline__ void cp16(uint32_t dst, const void* src) {
    asm volatile("cp.async.cg.shared.global [%0], [%1], 16;"
                 :: "r"(dst), "l"(src) : "memory");
}
__device__ __forceinline__ void ldm4(uint32_t& r0, uint32_t& r1,
                                     uint32_t& r2, uint32_t& r3, uint32_t a) {
    asm volatile("ldmatrix.sync.aligned.m8n8.x4.shared.b16 {%0,%1,%2,%3}, [%4];"
                 : "=r"(r0), "=r"(r1), "=r"(r2), "=r"(r3) : "r"(a));
}
__device__ __forceinline__ void ldm4t(uint32_t& r0, uint32_t& r1,
                                      uint32_t& r2, uint32_t& r3, uint32_t a) {
    asm volatile("ldmatrix.sync.aligned.m8n8.x4.trans.shared.b16 {%0,%1,%2,%3}, [%4];"
                 : "=r"(r0), "=r"(r1), "=r"(r2), "=r"(r3) : "r"(a));
}
__device__ __forceinline__ void mma16(float4& d, const uint32_t* a,
                                      uint32_t b0, uint32_t b1) {
    asm volatile(
        "mma.sync.aligned.m16n8k16.row.col.f32.f16.f16.f32 "
        "{%0,%1,%2,%3},{%4,%5,%6,%7},{%8,%9},{%0,%1,%2,%3};"
        : "+f"(d.x), "+f"(d.y), "+f"(d.z), "+f"(d.w)
        : "r"(a[0]), "r"(a[1]), "r"(a[2]), "r"(a[3]), "r"(b0), "r"(b1));
}

// ---------------------------------------------------------------------------
// Stage 0: global max/min of U
// ---------------------------------------------------------------------------
__global__ void init_minmax_kernel() { g_minmax[0] = -INFINITY; g_minmax[1] = INFINITY; }

__device__ __forceinline__ void atomicMaxF(float* a, float v) {
    if (v >= 0.f) atomicMax((int*)a, __float_as_int(v));
    else          atomicMin((unsigned int*)a, __float_as_uint(v));
}
__device__ __forceinline__ void atomicMinF(float* a, float v) {
    if (v >= 0.f) atomicMin((int*)a, __float_as_int(v));
    else          atomicMax((unsigned int*)a, __float_as_uint(v));
}

__global__ void reduce_minmax_kernel(const float* __restrict__ U, int n) {
    float mx = -INFINITY, mn = INFINITY;
    for (int i = blockIdx.x * blockDim.x + threadIdx.x; i < n; i += gridDim.x * blockDim.x) {
        float v = U[i]; mx = fmaxf(mx, v); mn = fminf(mn, v);
    }
#pragma unroll
    for (int o = 16; o; o >>= 1) {
        mx = fmaxf(mx, __shfl_xor_sync(0xffffffffu, mx, o));
        mn = fminf(mn, __shfl_xor_sync(0xffffffffu, mn, o));
    }
    if ((threadIdx.x & 31) == 0) { atomicMaxF(&g_minmax[0], mx); atomicMinF(&g_minmax[1], mn); }
}

// ---------------------------------------------------------------------------
// Stage 1: m1 + shared gate g1
// ---------------------------------------------------------------------------
__device__ __forceinline__ float stable_sigmoid(float x) {
    if (x >= 0.f) return 1.f / (1.f + __expf(-x));
    float e = __expf(x); return e / (1.f + e);
}
__device__ __forceinline__ float gatef(float uu, float b) {
    float g  = __logf(uu / (1.f - uu));
    float bs = stable_sigmoid(g + b);
    float t  = __fadd_rn(__fmul_rn(bs, 1.4f), -0.2f);
    return fminf(fmaxf(t, 0.f), 1.f);
}

__global__ void compute_m1_kernel(const float* __restrict__ U,
                                  const float* __restrict__ bp,
                                  const float* __restrict__ uu) {
    int d = blockIdx.x * blockDim.x + threadIdx.x;
    if (d >= D_TOT) return;
    float s1 = (g_minmax[0] - g_minmax[1]) / 3.0f;
    float s = 0.f;
#pragma unroll
    for (int nn = 0; nn < N_MEM; nn++) s += s1 * rintf(U[nn * D_TOT + d] / s1);
    g_m1[d] = s * (1.0f / 6.0f);
    g_g1[d] = gatef(uu[6 * D_TOT + d], bp[6 * D_TOT + d]);
}

// ---------------------------------------------------------------------------
// Stage 2: gates + residual quantization -> staged fp32 weights
// ---------------------------------------------------------------------------
__global__ void compute_w_kernel(const float* __restrict__ U,
                                 const float* __restrict__ bp,
                                 const float* __restrict__ uu) {
    int idx = blockIdx.x * blockDim.x + threadIdx.x;
    if (idx >= N_MEM * D_TOT) return;
    int d  = idx % D_TOT;

    float s1 = (g_minmax[0] - g_minmax[1]) / 3.0f;
    float s2 = s1 / 5.0f;

    float Uv = U[idx];
    float v1 = s1 * rintf(Uv / s1);
    float v2 = s2 * rintf((Uv - g_m1[d]) / s2);

    float g0 = gatef(uu[idx], bp[idx]);
    g_ws[idx] = v1 * g0 + ((g0 > 0.f) ? v2 * g_g1[d] : 0.f);
}

// ---------------------------------------------------------------------------
// Stage 3: weight Winograd transform u = G g G^T -> g_wU[n][comp][oc][ic]
// ---------------------------------------------------------------------------
__global__ void wino_w_kernel() {
    int idx = blockIdx.x * blockDim.x + threadIdx.x;
    if (idx >= N_MEM * 128 * 128) return;
    int n  = idx >> 14;
    int r  = idx & 16383;
    int oc = r >> 7, ic = r & 127;

    const float* w = g_ws + (size_t)n * D_TOT + oc * 1152 + ic * 9;
    float g[9];
#pragma unroll
    for (int i = 0; i < 9; i++) g[i] = w[i];

    float T[4][3];
#pragma unroll
    for (int c = 0; c < 3; c++) {
        T[0][c] = g[c];
        T[1][c] = 0.5f * (g[c] + g[3 + c] + g[6 + c]);
        T[2][c] = 0.5f * (g[c] - g[3 + c] + g[6 + c]);
        T[3][c] = g[6 + c];
    }
    __half* up = g_wU + (((size_t)n * 16) * 128 + oc) * 128 + ic;
#pragma unroll
    for (int rr = 0; rr < 4; rr++) {
        float u0 = T[rr][0];
        float u1 = 0.5f * (T[rr][0] + T[rr][1] + T[rr][2]);
        float u2 = 0.5f * (T[rr][0] - T[rr][1] + T[rr][2]);
        float u3 = T[rr][2];
        up[(size_t)(rr * 4 + 0) * 16384] = __float2half_rn(u0);
        up[(size_t)(rr * 4 + 1) * 16384] = __float2half_rn(u1);
        up[(size_t)(rr * 4 + 2) * 16384] = __float2half_rn(u2);
        up[(size_t)(rr * 4 + 3) * 16384] = __float2half_rn(u3);
    }
}

// ---------------------------------------------------------------------------
// Stage 4: pad x -> g_xp[s][ic][66][72] fp16 (zero halo)
// ---------------------------------------------------------------------------
#define NH2 14598144            // 48*128*66*72/2
__global__ void pad_kernel(const float* __restrict__ x) {
    int idx = blockIdx.x * 256 + threadIdx.x;
    if (idx >= NH2) return;
    int col2  = idx % 36;
    int t     = idx / 36;
    int row   = t % 66;
    int plane = t / 66;
    int gy  = row - 1;
    int gx0 = 2 * col2 - 1;
    const float* xp = x + (size_t)plane * NPX + gy * 64;
    bool yok = (unsigned)gy < 64u;
    float f0 = (yok && (unsigned)gx0 < 64u)       ? xp[gx0]     : 0.f;
    float f1 = (yok && (unsigned)(gx0 + 1) < 64u) ? xp[gx0 + 1] : 0.f;
    ((__half2*)g_xp)[idx] = __floats2half2_rn(f0, f1);
}

// ---------------------------------------------------------------------------
// Stage 5: fused Winograd GEMM (input transform in-kernel).
//   CTA: (tile-row tg, oc-half ocg, sample s); 512 thr; warp = comp.
//   smem: A0[64K] A1[64K] B[32K] raw0[18K] raw1[18K] = 200704 B.
// ---------------------------------------------------------------------------
#define OFF_A0  0u
#define OFF_A1  65536u
#define OFF_B   131072u
#define OFF_R0  163840u
#define OFF_R1  182272u
#define SM_BYTES 200704

__device__ __forceinline__ void issue_chunk(int c, uint32_t sbase, int tid,
                                            const __half* Asrc, const __half* xpb,
                                            int tg) {
    uint32_t ab = sbase + ((c & 1) ? OFF_A1 : OFF_A0);
#pragma unroll
    for (int i = 0; i < 8; i++) {                       // A: [comp][oc][k32]
        int id  = tid + i * 512;
        int row = id >> 2, j = id & 3;                  // row = comp*64+oc
        int comp = row >> 6, oc = row & 63;
        const __half* src = Asrc + (size_t)comp * 16384 + oc * 128 + c * 32 + j * 8;
        cp16(ab + row * 64 + ((j ^ ((row >> 1) & 3)) << 4), src);
    }
    uint32_t rb = sbase + ((c & 1) ? OFF_R1 : OFF_R0);  // raw: [ic32][4r][72]
#pragma unroll
    for (int i = 0; i < 3; i++) {
        int id = tid + i * 512;
        if (id < 1152) {
            int ic  = id / 36;
            int rem = id - ic * 36;
            int r   = rem / 9, j = rem - r * 9;
            const __half* src = xpb + (size_t)(c * 32 + ic) * PPL + (2 * tg + r) * 72 + j * 8;
            cp16(rb + (ic * 4 + r) * 144 + j * 16, src);
        }
    }
    asm volatile("cp.async.commit_group;" ::: "memory");
}

__global__ __launch_bounds__(512, 1)
void wino_fused_kernel(float* __restrict__ out) {
    extern __shared__ char smc[];
    uint32_t sbase = smem_u32(smc);

    const int tid = threadIdx.x;
    const int tg  = blockIdx.x;          // tile row (0..31)
    const int ocg = blockIdx.y;
    const int s   = blockIdx.z;
    const int n   = s % N_MEM;
    const int wid = tid >> 5;            // comp
    const int l   = tid & 31;

    const __half* Asrc = g_wU + ((size_t)n * 16) * 16384 + ocg * 64 * 128;
    const __half* xpb  = g_xp + (size_t)s * 128 * PPL;

    float4 acc[4][4];
#pragma unroll
    for (int i = 0; i < 4; i++)
#pragma unroll
        for (int j = 0; j < 4; j++) acc[i][j] = make_float4(0.f, 0.f, 0.f, 0.f);

    issue_chunk(0, sbase, tid, Asrc, xpb, tg);
    issue_chunk(1, sbase, tid, Asrc, xpb, tg);

#pragma unroll
    for (int c = 0; c < 4; c++) {
        if (c < 3) asm volatile("cp.async.wait_group 1;" ::: "memory");
        else       asm volatile("cp.async.wait_group 0;" ::: "memory");
        __syncthreads();

        // ---- in-smem input transform: raw[c&1] -> B (all 16 comps) ----
        {
            const __half* raw = (const __half*)(smc + ((c & 1) ? OFF_R1 : OFF_R0));
            __half* Bp = (__half*)(smc + OFF_B);
#pragma unroll
            for (int i = 0; i < 2; i++) {
                int p  = tid + i * 512;
                int tx = p & 31, k = p >> 5;
                float X[4][4];
#pragma unroll
                for (int r = 0; r < 4; r++) {
                    const __half* rr = raw + k * 288 + r * 72 + 2 * tx;
#pragma unroll
                    for (int cc = 0; cc < 4; cc++) X[r][cc] = __half2float(rr[cc]);
                }
                float T[4][4];
#pragma unroll
                for (int cc = 0; cc < 4; cc++) {
                    T[0][cc] = X[0][cc] - X[2][cc];
                    T[1][cc] = X[1][cc] + X[2][cc];
                    T[2][cc] = X[2][cc] - X[1][cc];
                    T[3][cc] = X[1][cc] - X[3][cc];
                }
                int swb = (((tx >> 3) ^ ((k >> 1) & 3)) << 3) + (tx & 7);
#pragma unroll
                for (int r = 0; r < 4; r++) {
                    float d0 = T[r][0] - T[r][2];
                    float d1 = T[r][1] + T[r][2];
                    float d2 = T[r][2] - T[r][1];
                    float d3 = T[r][1] - T[r][3];
                    int rb = ((r * 4) * 32 + k) * 32 + swb;
                    Bp[rb]           = __float2half_rn(d0);
                    Bp[rb + 1024]    = __float2half_rn(d1);   // comp+1: +32 rows*32
                    Bp[rb + 2048]    = __float2half_rn(d2);
                    Bp[rb + 3072]    = __float2half_rn(d3);
                }
            }
        }
        __syncthreads();

        // ---- GEMM chunk c ----
        uint32_t Ab = sbase + ((c & 1) ? OFF_A1 : OFF_A0);
        uint32_t Bb = sbase + OFF_B;
#pragma unroll
        for (int kf = 0; kf < 2; kf++) {
            uint32_t a[4][4];
#pragma unroll
            for (int mt = 0; mt < 4; mt++) {
                int row  = wid * 64 + mt * 16 + (l & 15);
                int slot = (kf * 2 + ((l >> 4) & 1)) ^ ((row >> 1) & 3);
                ldm4(a[mt][0], a[mt][1], a[mt][2], a[mt][3], Ab + row * 64 + slot * 16);
            }
#pragma unroll
            for (int nf = 0; nf < 2; nf++) {
                int row  = wid * 32 + kf * 16 + (l & 15);
                int slot = (nf * 2 + ((l >> 4) & 1)) ^ ((row >> 1) & 3);
                uint32_t b0, b1, b2, b3;
                ldm4t(b0, b1, b2, b3, Bb + row * 64 + slot * 16);
#pragma unroll
                for (int mt = 0; mt < 4; mt++) {
                    mma16(acc[mt][nf * 2],     a[mt], b0, b1);
                    mma16(acc[mt][nf * 2 + 1], a[mt], b2, b3);
                }
            }
        }
        __syncthreads();
        if (c + 2 < 4) issue_chunk(c + 2, sbase, tid, Asrc, xpb, tg);
    }

    // ---- fused output transform (R7-validated): stage, fold, store ----
    float* smf = (float*)smc;            // 16 x 64 x 32 fp32 = 128 KB (aliases A)
#pragma unroll
    for (int mt = 0; mt < 4; mt++)
#pragma unroll
        for (int nb = 0; nb < 4; nb++) {
            int ocl  = mt * 16 + (l >> 2);
            int tile = nb * 8 + (l & 3) * 2;
            float4 d = acc[mt][nb];
            *(float2*)&smf[wid * 2048 + ocl * 32 + tile]       = make_float2(d.x, d.y);
            *(float2*)&smf[wid * 2048 + (ocl + 8) * 32 + tile] = make_float2(d.z, d.w);
        }
    __syncthreads();

#pragma unroll
    for (int k = 0; k < 4; k++) {
        int p    = tid + k * 512;
        int ocl  = p >> 5;
        int tile = p & 31;
        float m[16];
#pragma unroll
        for (int c = 0; c < 16; c++) m[c] = smf[c * 2048 + ocl * 32 + tile];

        float p0[4], p1[4];
#pragma unroll
        for (int i = 0; i < 4; i++) {
            p0[i] = m[i * 4 + 0] + m[i * 4 + 1] + m[i * 4 + 2];
            p1[i] = m[i * 4 + 1] - m[i * 4 + 2] - m[i * 4 + 3];
        }
        float y00 = p0[0] + p0[1] + p0[2];
        float y01 = p1[0] + p1[1] + p1[2];
        float y10 = p0[1] - p0[2] - p0[3];
        float y11 = p1[1] - p1[2] - p1[3];

        float* op = out + (((size_t)s * 128 + ocg * 64 + ocl) * 64 + 2 * tg) * 64 + 2 * tile;
        *(float2*)op        = make_float2(y00, y01);
        *(float2*)(op + 64) = make_float2(y10, y11);
    }
}

// ---------------------------------------------------------------------------
extern "C" void kernel_launch(void* const* d_in, const int* in_sizes, int n_in,
                              void* d_out, int out_size) {
    const float* x  = (const float*)d_in[0];   // (48,128,64,64)
    const float* U  = (const float*)d_in[1];
    const float* bp = (const float*)d_in[2];
    const float* u  = (const float*)d_in[3];
    float* out = (float*)d_out;

    cudaFuncSetAttribute(wino_fused_kernel, cudaFuncAttributeMaxDynamicSharedMemorySize, SM_BYTES);

    init_minmax_kernel<<<1, 1>>>();
    reduce_minmax_kernel<<<432, 256>>>(U, N_MEM * D_TOT);
    compute_m1_kernel<<<(D_TOT + 255) / 256, 256>>>(U, bp, u);
    compute_w_kernel<<<(N_MEM * D_TOT + 255) / 256, 256>>>(U, bp, u);
    wino_w_kernel<<<(N_MEM * 128 * 128 + 255) / 256, 256>>>();
    pad_kernel<<<(NH2 + 255) / 256, 256>>>(x);

    wino_fused_kernel<<<dim3(32, 2, 48), 512, SM_BYTES>>>(out);
}